// round 16
// baseline (speedup 1.0000x reference)
#include <cuda_runtime.h>

// Problem constants: T=4, L=4, N=2048, E=65536, H=64, C=2
#define TT 4
#define LL 4
#define NN 2048
#define EE 65536
#define HH 64
#define TL (TT*LL)

// ---------------- device scratch ----------------
// stride-8 rows (32B): [0]=sum(w*p), [1]=sum(w*q), [2]=sum(w), [3]=0 (v4 pad), [4..7] unused.
// One 32B LTS sector per (t,l,n) row -> single red.v4 per edge-layer, no sector sharing.
// Zero at module load; node_kernel restores zeros every call.
__device__ float g_sums[TL * NN * 8];
__device__ float g_val[TT * 2 * LL * NN];   // [T][2*L*N]

// ---------------- K1: edge pass — folded coefs, ONE red.v4 per edge-layer ----------------
// Prefetches the first 4KB of every Wfc row into L2 (64 MB), issued after the coef
// phase (R14/R15 A-B test: post-sync placement beats top-of-kernel by ~1.2us).
__global__ void __launch_bounds__(256) edge_kernel(const float* __restrict__ x,
                                                   const float* __restrict__ ea,
                                                   const int* __restrict__ src,
                                                   const int* __restrict__ tgt,
                                                   const float* __restrict__ Wq,
                                                   const float* __restrict__ bq,
                                                   const float* __restrict__ Wk,
                                                   const float* __restrict__ bk,
                                                   const float* __restrict__ We,
                                                   const float* __restrict__ Wv,
                                                   const float* __restrict__ bv,
                                                   const float* __restrict__ Wfc)
{
    __shared__ float sa[4][16];     // coefA per layer (t fixed per block)
    __shared__ float sp[4][12];     // coefP[0..4], coefQ at [5..9]

    int tid = threadIdx.x;
    int wid = tid >> 5, lane = tid & 31;
    int idx = blockIdx.x * 256 + tid;   // 0 .. T*E-1
    int t = (blockIdx.x * 256) >> 16;   // constant per block (256 | E)

    if (wid < 4) {
        // coefA for tl = t*4 + wid
        int tl = t * LL + wid;
        const float* wq0 = Wq + (size_t)tl * 2 * HH;
        const float* wq1 = wq0 + HH;
        const float* bqp = bq + (size_t)tl * HH;
        float q0a = wq0[lane], q0b = wq0[lane + 32];
        float q1a = wq1[lane], q1b = wq1[lane + 32];
        float bba = bqp[lane], bbb = bqp[lane + 32];

        const float* Xs[5];
        Xs[0] = Wk + (size_t)tl * 2 * HH;
        Xs[1] = Xs[0] + HH;
        Xs[2] = We + (size_t)tl * 2 * HH;
        Xs[3] = Xs[2] + HH;
        Xs[4] = bk + (size_t)tl * HH;

        float pa[15];
#pragma unroll
        for (int k = 0; k < 5; k++) {
            float xa = Xs[k][lane], xb = Xs[k][lane + 32];
            pa[3*k + 0] = q0a * xa + q0b * xb;
            pa[3*k + 1] = q1a * xa + q1b * xb;
            pa[3*k + 2] = bba * xa + bbb * xb;
        }
#pragma unroll
        for (int off = 16; off > 0; off >>= 1)
#pragma unroll
            for (int i = 0; i < 15; i++)
                pa[i] += __shfl_down_sync(0xffffffffu, pa[i], off);
        if (lane == 0) {
#pragma unroll
            for (int i = 0; i < 15; i++) sa[wid][i] = pa[i];
            sa[wid][15] = 0.0f;
        }
    } else {
        // coefP/Q for tl = t*4 + (wid-4)
        int lw = wid - 4;
        int tl = t * LL + lw;
        const float* Ys[5];
        Ys[0] = Wv + (size_t)tl * 2 * HH;
        Ys[1] = Ys[0] + HH;
        Ys[2] = We + (size_t)tl * 2 * HH;
        Ys[3] = Ys[2] + HH;
        Ys[4] = bv + (size_t)tl * HH;

        float ph[10];
#pragma unroll
        for (int k = 0; k < 5; k++) {
            ph[k]     = Ys[k][lane];            // low half (h<32)
            ph[5 + k] = Ys[k][lane + 32];       // high half
        }
#pragma unroll
        for (int off = 16; off > 0; off >>= 1)
#pragma unroll
            for (int i = 0; i < 10; i++)
                ph[i] += __shfl_down_sync(0xffffffffu, ph[i], off);
        if (lane == 0)
#pragma unroll
            for (int i = 0; i < 10; i++) sp[lw][i] = ph[i];
    }
    __syncthreads();

    // Wfc L2 prefetch: first 4KB of each row = 32 x 128B sectors/row,
    // 16384 rows -> 524288 sectors, 2 per thread across 262144 threads.
    {
        int gtid = blockIdx.x * 256 + tid;
#pragma unroll
        for (int k = 0; k < 2; k++) {
            int sec = gtid * 2 + k;
            int row = sec >> 5;
            int s   = sec & 31;
            const char* p = (const char*)Wfc + (size_t)row * 65536 + (size_t)s * 128;
            asm volatile("prefetch.global.L2 [%0];" :: "l"(p));
        }
    }

    int s = src[idx];
    int g = tgt[idx];
    float xs0 = x[2 * s], xs1 = x[2 * s + 1];
    float ea0 = ea[2 * idx], ea1 = ea[2 * idx + 1];
    int tn = t * NN + g;
    float xt0 = x[2 * tn], xt1 = x[2 * tn + 1];

#pragma unroll
    for (int l = 0; l < LL; l++) {
        const float* c = sa[l];
        float A0 = fmaf(c[0],  xt0, fmaf(c[1],  xt1, c[2]));
        float A1 = fmaf(c[3],  xt0, fmaf(c[4],  xt1, c[5]));
        float A2 = fmaf(c[6],  xt0, fmaf(c[7],  xt1, c[8]));
        float A3 = fmaf(c[9],  xt0, fmaf(c[10], xt1, c[11]));
        float A4 = fmaf(c[12], xt0, fmaf(c[13], xt1, c[14]));
        float alpha = (A0 * xs0 + A1 * xs1 + A2 * ea0 + A3 * ea1 + A4) * 0.125f;
        float w = expf(alpha);   // |alpha| is O(1): shift-free softmax is safe

        const float* hh = sp[l];
        float p = fmaf(hh[0], xs0, fmaf(hh[1], xs1, fmaf(hh[2], ea0, fmaf(hh[3], ea1, hh[4]))));
        float q = fmaf(hh[5], xs0, fmaf(hh[6], xs1, fmaf(hh[7], ea0, fmaf(hh[8], ea1, hh[9]))));

        float* sm = &g_sums[((t * LL + l) * NN + g) * 8];
        asm volatile("red.global.add.v4.f32 [%0], {%1, %2, %3, %4};"
                     :: "l"(sm), "f"(w * p), "f"(w * q), "f"(w), "f"(0.0f)
                     : "memory");
    }
}

// ---------------- K2: node pass — normalize, add skip, restore zeros, prefetch more Wfc ----------------
__global__ void __launch_bounds__(256) node_kernel(const float* __restrict__ x,
                                                   const float* __restrict__ Wsk,
                                                   const float* __restrict__ bsk,
                                                   const float* __restrict__ Wfc)
{
    __shared__ float h[8];   // skip coefs: [0..2]={Wsk0,Wsk1,bsk} low half, [3..5]=high half

    int tid = threadIdx.x;
    int idx = blockIdx.x * 256 + tid;   // 0 .. T*L*N-1
    int tl = (blockIdx.x * 256) >> 11;  // constant per block (256 | N)
    int t = tl >> 2;
    int l = tl & 3;
    int n = idx & (NN - 1);

    // Continue the Wfc prefetch: next 3KB of each row (bytes 4096..7167) =
    // 24 sectors/row x 16384 rows = 393216 sectors, 12 per thread across 32768
    // threads. Total prefetched = 112 MB < 126 MB L2, so the later wave does not
    // evict the head-of-row bytes GEMV reads first.
    {
#pragma unroll
        for (int k = 0; k < 12; k++) {
            int sec = idx * 12 + k;
            int row = sec / 24;
            int s   = 32 + (sec - row * 24);
            const char* p = (const char*)Wfc + (size_t)row * 65536 + (size_t)s * 128;
            asm volatile("prefetch.global.L2 [%0];" :: "l"(p));
        }
    }

    if (tid < 32) {
        int lane = tid;
        const float* Ys[3];
        Ys[0] = Wsk + (size_t)tl * 2 * HH;
        Ys[1] = Ys[0] + HH;
        Ys[2] = bsk + (size_t)tl * HH;

        float ph[6];
#pragma unroll
        for (int k = 0; k < 3; k++) {
            ph[k]     = Ys[k][lane];
            ph[3 + k] = Ys[k][lane + 32];
        }
#pragma unroll
        for (int off = 16; off > 0; off >>= 1)
#pragma unroll
            for (int i = 0; i < 6; i++)
                ph[i] += __shfl_down_sync(0xffffffffu, ph[i], off);
        if (lane == 0)
#pragma unroll
            for (int i = 0; i < 6; i++) h[i] = ph[i];
    }
    __syncthreads();

    float* smp = &g_sums[idx * 8];
    float4 v = *reinterpret_cast<float4*>(smp);   // {sum_wp, sum_wq, sum_w, 0}

    // restore zeros for next replay (only first 16B are ever written)
    *reinterpret_cast<float4*>(smp) = make_float4(0.f, 0.f, 0.f, 0.f);

    float inv = 1.0f / (v.z + 1e-16f);

    int tn = t * NN + n;
    float xt0 = x[2 * tn], xt1 = x[2 * tn + 1];

    float P = v.x * inv + fmaf(h[0], xt0, fmaf(h[1], xt1, h[2]));
    float Q = v.y * inv + fmaf(h[3], xt0, fmaf(h[4], xt1, h[5]));

    int vo = t * (2 * LL * NN) + 2 * (l * NN + n);
    g_val[vo]     = P;
    g_val[vo + 1] = Q;
}

// ---------------- K3: GEMV — unchanged (8 warps x 2 rows, __ldcs) ----------------
__global__ void __launch_bounds__(256) gemv_kernel(const float* __restrict__ Wfc,
                                                   const float* __restrict__ bfc,
                                                   float* __restrict__ out)
{
    const int t = blockIdx.y;
    const int rowBase = blockIdx.x * 16;
    __shared__ float4 sv[1024];                    // 16 KB chunk of val

    int tid = threadIdx.x;
    int lane = tid & 31;
    int w = tid >> 5;
    int r0 = rowBase + w;
    int r1 = rowBase + 8 + w;

    const float4* val4 = reinterpret_cast<const float4*>(g_val + t * (2 * LL * NN));
    const float4* W0 = reinterpret_cast<const float4*>(Wfc + ((size_t)(t * 4096 + r0)) * 16384);
    const float4* W1 = reinterpret_cast<const float4*>(Wfc + ((size_t)(t * 4096 + r1)) * 16384);

    float4 a0 = make_float4(0.f, 0.f, 0.f, 0.f);
    float4 a1 = make_float4(0.f, 0.f, 0.f, 0.f);

#pragma unroll
    for (int c = 0; c < 4; c++) {
        for (int j = tid; j < 1024; j += 256)
            sv[j] = val4[c * 1024 + j];
        __syncthreads();

        const int base = c * 1024;
#pragma unroll 8
        for (int j = lane; j < 1024; j += 32) {
            float4 v  = sv[j];
            float4 w0 = __ldcs(&W0[base + j]);   // streaming: no-reuse 1GB scan
            float4 w1 = __ldcs(&W1[base + j]);
            a0.x = fmaf(w0.x, v.x, a0.x);
            a0.y = fmaf(w0.y, v.y, a0.y);
            a0.z = fmaf(w0.z, v.z, a0.z);
            a0.w = fmaf(w0.w, v.w, a0.w);
            a1.x = fmaf(w1.x, v.x, a1.x);
            a1.y = fmaf(w1.y, v.y, a1.y);
            a1.z = fmaf(w1.z, v.z, a1.z);
            a1.w = fmaf(w1.w, v.w, a1.w);
        }
        __syncthreads();
    }

    float s0 = (a0.x + a0.y) + (a0.z + a0.w);
    float s1 = (a1.x + a1.y) + (a1.z + a1.w);
#pragma unroll
    for (int off = 16; off > 0; off >>= 1) {
        s0 += __shfl_down_sync(0xffffffffu, s0, off);
        s1 += __shfl_down_sync(0xffffffffu, s1, off);
    }
    if (lane == 0) {
        out[t * 4096 + r0] = s0 + bfc[t * 4096 + r0];
        out[t * 4096 + r1] = s1 + bfc[t * 4096 + r1];
    }
}

// ---------------- launch: 3 kernels, single stream ----------------
extern "C" void kernel_launch(void* const* d_in, const int* in_sizes, int n_in,
                              void* d_out, int out_size)
{
    const float* x    = (const float*)d_in[0];
    const float* ea   = (const float*)d_in[1];
    const int*   src  = (const int*)  d_in[2];
    const int*   tgt  = (const int*)  d_in[3];
    const float* Wq   = (const float*)d_in[4];
    const float* bq   = (const float*)d_in[5];
    const float* Wk   = (const float*)d_in[6];
    const float* bk   = (const float*)d_in[7];
    const float* Wv   = (const float*)d_in[8];
    const float* bv   = (const float*)d_in[9];
    const float* We   = (const float*)d_in[10];
    const float* Wsk  = (const float*)d_in[11];
    const float* bsk  = (const float*)d_in[12];
    const float* Wfc  = (const float*)d_in[13];
    const float* bfc  = (const float*)d_in[14];
    float* out = (float*)d_out;

    edge_kernel<<<(TT * EE) / 256, 256>>>(x, ea, src, tgt, Wq, bq, Wk, bk, We, Wv, bv, Wfc);
    node_kernel<<<(TL * NN) / 256, 256>>>(x, Wsk, bsk, Wfc);
    gemv_kernel<<<dim3(256, TT), 256>>>(Wfc, bfc, out);
}

// round 17
// speedup vs baseline: 1.0002x; 1.0002x over previous
#include <cuda_runtime.h>

// Problem constants: T=4, L=4, N=2048, E=65536, H=64, C=2
#define TT 4
#define LL 4
#define NN 2048
#define EE 65536
#define HH 64
#define TL (TT*LL)

// ---------------- device scratch ----------------
// stride-8 rows (32B): [0]=sum(w*p), [1]=sum(w*q), [2]=sum(w), [3]=0 (v4 pad), [4..7] unused.
// One 32B LTS sector per (t,l,n) row -> single red.v4 per edge-layer, no sector sharing.
// Zero at module load; node_kernel restores zeros every call.
__device__ float g_sums[TL * NN * 8];
__device__ float g_val[TT * 2 * LL * NN];   // [T][2*L*N]

// ---------------- K1: edge pass — folded coefs, ONE red.v4 per edge-layer ----------------
// Prefetches the first 4KB of every Wfc row into L2 (64 MB), issued after the coef
// phase (R14/R15/R16 A-B: post-sync placement is 1.2us better than top-of-kernel).
__global__ void __launch_bounds__(256) edge_kernel(const float* __restrict__ x,
                                                   const float* __restrict__ ea,
                                                   const int* __restrict__ src,
                                                   const int* __restrict__ tgt,
                                                   const float* __restrict__ Wq,
                                                   const float* __restrict__ bq,
                                                   const float* __restrict__ Wk,
                                                   const float* __restrict__ bk,
                                                   const float* __restrict__ We,
                                                   const float* __restrict__ Wv,
                                                   const float* __restrict__ bv,
                                                   const float* __restrict__ Wfc)
{
    __shared__ float sa[4][16];     // coefA per layer (t fixed per block)
    __shared__ float sp[4][12];     // coefP[0..4], coefQ at [5..9]

    int tid = threadIdx.x;
    int wid = tid >> 5, lane = tid & 31;
    int idx = blockIdx.x * 256 + tid;   // 0 .. T*E-1
    int t = (blockIdx.x * 256) >> 16;   // constant per block (256 | E)

    if (wid < 4) {
        // coefA for tl = t*4 + wid
        int tl = t * LL + wid;
        const float* wq0 = Wq + (size_t)tl * 2 * HH;
        const float* wq1 = wq0 + HH;
        const float* bqp = bq + (size_t)tl * HH;
        float q0a = wq0[lane], q0b = wq0[lane + 32];
        float q1a = wq1[lane], q1b = wq1[lane + 32];
        float bba = bqp[lane], bbb = bqp[lane + 32];

        const float* Xs[5];
        Xs[0] = Wk + (size_t)tl * 2 * HH;
        Xs[1] = Xs[0] + HH;
        Xs[2] = We + (size_t)tl * 2 * HH;
        Xs[3] = Xs[2] + HH;
        Xs[4] = bk + (size_t)tl * HH;

        float pa[15];
#pragma unroll
        for (int k = 0; k < 5; k++) {
            float xa = Xs[k][lane], xb = Xs[k][lane + 32];
            pa[3*k + 0] = q0a * xa + q0b * xb;
            pa[3*k + 1] = q1a * xa + q1b * xb;
            pa[3*k + 2] = bba * xa + bbb * xb;
        }
#pragma unroll
        for (int off = 16; off > 0; off >>= 1)
#pragma unroll
            for (int i = 0; i < 15; i++)
                pa[i] += __shfl_down_sync(0xffffffffu, pa[i], off);
        if (lane == 0) {
#pragma unroll
            for (int i = 0; i < 15; i++) sa[wid][i] = pa[i];
            sa[wid][15] = 0.0f;
        }
    } else {
        // coefP/Q for tl = t*4 + (wid-4)
        int lw = wid - 4;
        int tl = t * LL + lw;
        const float* Ys[5];
        Ys[0] = Wv + (size_t)tl * 2 * HH;
        Ys[1] = Ys[0] + HH;
        Ys[2] = We + (size_t)tl * 2 * HH;
        Ys[3] = Ys[2] + HH;
        Ys[4] = bv + (size_t)tl * HH;

        float ph[10];
#pragma unroll
        for (int k = 0; k < 5; k++) {
            ph[k]     = Ys[k][lane];            // low half (h<32)
            ph[5 + k] = Ys[k][lane + 32];       // high half
        }
#pragma unroll
        for (int off = 16; off > 0; off >>= 1)
#pragma unroll
            for (int i = 0; i < 10; i++)
                ph[i] += __shfl_down_sync(0xffffffffu, ph[i], off);
        if (lane == 0)
#pragma unroll
            for (int i = 0; i < 10; i++) sp[lw][i] = ph[i];
    }
    __syncthreads();

    // Wfc L2 prefetch: first 4KB of each row = 32 x 128B sectors/row,
    // 16384 rows -> 524288 sectors, 2 per thread across 262144 threads.
    {
        int gtid = blockIdx.x * 256 + tid;
#pragma unroll
        for (int k = 0; k < 2; k++) {
            int sec = gtid * 2 + k;
            int row = sec >> 5;
            int s   = sec & 31;
            const char* p = (const char*)Wfc + (size_t)row * 65536 + (size_t)s * 128;
            asm volatile("prefetch.global.L2 [%0];" :: "l"(p));
        }
    }

    int s = src[idx];
    int g = tgt[idx];
    float xs0 = x[2 * s], xs1 = x[2 * s + 1];
    float ea0 = ea[2 * idx], ea1 = ea[2 * idx + 1];
    int tn = t * NN + g;
    float xt0 = x[2 * tn], xt1 = x[2 * tn + 1];

#pragma unroll
    for (int l = 0; l < LL; l++) {
        const float* c = sa[l];
        float A0 = fmaf(c[0],  xt0, fmaf(c[1],  xt1, c[2]));
        float A1 = fmaf(c[3],  xt0, fmaf(c[4],  xt1, c[5]));
        float A2 = fmaf(c[6],  xt0, fmaf(c[7],  xt1, c[8]));
        float A3 = fmaf(c[9],  xt0, fmaf(c[10], xt1, c[11]));
        float A4 = fmaf(c[12], xt0, fmaf(c[13], xt1, c[14]));
        float alpha = (A0 * xs0 + A1 * xs1 + A2 * ea0 + A3 * ea1 + A4) * 0.125f;
        float w = expf(alpha);   // |alpha| is O(1): shift-free softmax is safe

        const float* hh = sp[l];
        float p = fmaf(hh[0], xs0, fmaf(hh[1], xs1, fmaf(hh[2], ea0, fmaf(hh[3], ea1, hh[4]))));
        float q = fmaf(hh[5], xs0, fmaf(hh[6], xs1, fmaf(hh[7], ea0, fmaf(hh[8], ea1, hh[9]))));

        float* sm = &g_sums[((t * LL + l) * NN + g) * 8];
        asm volatile("red.global.add.v4.f32 [%0], {%1, %2, %3, %4};"
                     :: "l"(sm), "f"(w * p), "f"(w * q), "f"(w), "f"(0.0f)
                     : "memory");
    }
}

// ---------------- K2: node pass — normalize, add skip, restore zeros, prefetch more Wfc ----------------
__global__ void __launch_bounds__(256) node_kernel(const float* __restrict__ x,
                                                   const float* __restrict__ Wsk,
                                                   const float* __restrict__ bsk,
                                                   const float* __restrict__ Wfc)
{
    __shared__ float h[8];   // skip coefs: [0..2]={Wsk0,Wsk1,bsk} low half, [3..5]=high half

    int tid = threadIdx.x;
    int idx = blockIdx.x * 256 + tid;   // 0 .. T*L*N-1
    int tl = (blockIdx.x * 256) >> 11;  // constant per block (256 | N)
    int t = tl >> 2;
    int l = tl & 3;
    int n = idx & (NN - 1);

    // Continue the Wfc prefetch: next 2KB of each row (bytes 4096..6143) =
    // 16 sectors/row x 16384 rows = 262144 sectors, 8 per thread across 32768
    // threads. 32 MB — the measured optimum (48 MB crosses the L2 retention
    // cliff and evicts the head-of-row lines the GEMV reads first).
    {
#pragma unroll
        for (int k = 0; k < 8; k++) {
            int sec = idx * 8 + k;
            int row = sec >> 4;
            int s   = 32 + (sec & 15);
            const char* p = (const char*)Wfc + (size_t)row * 65536 + (size_t)s * 128;
            asm volatile("prefetch.global.L2 [%0];" :: "l"(p));
        }
    }

    if (tid < 32) {
        int lane = tid;
        const float* Ys[3];
        Ys[0] = Wsk + (size_t)tl * 2 * HH;
        Ys[1] = Ys[0] + HH;
        Ys[2] = bsk + (size_t)tl * HH;

        float ph[6];
#pragma unroll
        for (int k = 0; k < 3; k++) {
            ph[k]     = Ys[k][lane];
            ph[3 + k] = Ys[k][lane + 32];
        }
#pragma unroll
        for (int off = 16; off > 0; off >>= 1)
#pragma unroll
            for (int i = 0; i < 6; i++)
                ph[i] += __shfl_down_sync(0xffffffffu, ph[i], off);
        if (lane == 0)
#pragma unroll
            for (int i = 0; i < 6; i++) h[i] = ph[i];
    }
    __syncthreads();

    float* smp = &g_sums[idx * 8];
    float4 v = *reinterpret_cast<float4*>(smp);   // {sum_wp, sum_wq, sum_w, 0}

    // restore zeros for next replay (only first 16B are ever written)
    *reinterpret_cast<float4*>(smp) = make_float4(0.f, 0.f, 0.f, 0.f);

    float inv = 1.0f / (v.z + 1e-16f);

    int tn = t * NN + n;
    float xt0 = x[2 * tn], xt1 = x[2 * tn + 1];

    float P = v.x * inv + fmaf(h[0], xt0, fmaf(h[1], xt1, h[2]));
    float Q = v.y * inv + fmaf(h[3], xt0, fmaf(h[4], xt1, h[5]));

    int vo = t * (2 * LL * NN) + 2 * (l * NN + n);
    g_val[vo]     = P;
    g_val[vo + 1] = Q;
}

// ---------------- K3: GEMV — unchanged (8 warps x 2 rows, __ldcs) ----------------
__global__ void __launch_bounds__(256) gemv_kernel(const float* __restrict__ Wfc,
                                                   const float* __restrict__ bfc,
                                                   float* __restrict__ out)
{
    const int t = blockIdx.y;
    const int rowBase = blockIdx.x * 16;
    __shared__ float4 sv[1024];                    // 16 KB chunk of val

    int tid = threadIdx.x;
    int lane = tid & 31;
    int w = tid >> 5;
    int r0 = rowBase + w;
    int r1 = rowBase + 8 + w;

    const float4* val4 = reinterpret_cast<const float4*>(g_val + t * (2 * LL * NN));
    const float4* W0 = reinterpret_cast<const float4*>(Wfc + ((size_t)(t * 4096 + r0)) * 16384);
    const float4* W1 = reinterpret_cast<const float4*>(Wfc + ((size_t)(t * 4096 + r1)) * 16384);

    float4 a0 = make_float4(0.f, 0.f, 0.f, 0.f);
    float4 a1 = make_float4(0.f, 0.f, 0.f, 0.f);

#pragma unroll
    for (int c = 0; c < 4; c++) {
        for (int j = tid; j < 1024; j += 256)
            sv[j] = val4[c * 1024 + j];
        __syncthreads();

        const int base = c * 1024;
#pragma unroll 8
        for (int j = lane; j < 1024; j += 32) {
            float4 v  = sv[j];
            float4 w0 = __ldcs(&W0[base + j]);   // streaming: no-reuse 1GB scan
            float4 w1 = __ldcs(&W1[base + j]);
            a0.x = fmaf(w0.x, v.x, a0.x);
            a0.y = fmaf(w0.y, v.y, a0.y);
            a0.z = fmaf(w0.z, v.z, a0.z);
            a0.w = fmaf(w0.w, v.w, a0.w);
            a1.x = fmaf(w1.x, v.x, a1.x);
            a1.y = fmaf(w1.y, v.y, a1.y);
            a1.z = fmaf(w1.z, v.z, a1.z);
            a1.w = fmaf(w1.w, v.w, a1.w);
        }
        __syncthreads();
    }

    float s0 = (a0.x + a0.y) + (a0.z + a0.w);
    float s1 = (a1.x + a1.y) + (a1.z + a1.w);
#pragma unroll
    for (int off = 16; off > 0; off >>= 1) {
        s0 += __shfl_down_sync(0xffffffffu, s0, off);
        s1 += __shfl_down_sync(0xffffffffu, s1, off);
    }
    if (lane == 0) {
        out[t * 4096 + r0] = s0 + bfc[t * 4096 + r0];
        out[t * 4096 + r1] = s1 + bfc[t * 4096 + r1];
    }
}

// ---------------- launch: 3 kernels, single stream ----------------
extern "C" void kernel_launch(void* const* d_in, const int* in_sizes, int n_in,
                              void* d_out, int out_size)
{
    const float* x    = (const float*)d_in[0];
    const float* ea   = (const float*)d_in[1];
    const int*   src  = (const int*)  d_in[2];
    const int*   tgt  = (const int*)  d_in[3];
    const float* Wq   = (const float*)d_in[4];
    const float* bq   = (const float*)d_in[5];
    const float* Wk   = (const float*)d_in[6];
    const float* bk   = (const float*)d_in[7];
    const float* Wv   = (const float*)d_in[8];
    const float* bv   = (const float*)d_in[9];
    const float* We   = (const float*)d_in[10];
    const float* Wsk  = (const float*)d_in[11];
    const float* bsk  = (const float*)d_in[12];
    const float* Wfc  = (const float*)d_in[13];
    const float* bfc  = (const float*)d_in[14];
    float* out = (float*)d_out;

    edge_kernel<<<(TT * EE) / 256, 256>>>(x, ea, src, tgt, Wq, bq, Wk, bk, We, Wv, bv, Wfc);
    node_kernel<<<(TL * NN) / 256, 256>>>(x, Wsk, bsk, Wfc);
    gemv_kernel<<<dim3(256, TT), 256>>>(Wfc, bfc, out);
}